// round 14
// baseline (speedup 1.0000x reference)
#include <cuda_runtime.h>
#include <cuda_bf16.h>
#include <stdint.h>

#define S_LEN   2048
#define DH      64
#define HEADS   16
#define BATCH   2
#define DMODEL  1024

#define BM      128     // query rows / output rows per CTA
#define BN      64      // key tile / output cols per CTA
#define PADH    72      // bf16 row stride (144B: 16B-aligned, conflict-free ldmatrix)

#define NTOK    (BATCH * S_LEN * DMODEL)   // 4M elements

// Persistent split-bf16 operands (hi + lo, lo = fp32 - bf16(hi))
__device__ __nv_bfloat16 g_Qh[NTOK], g_Ql[NTOK];
__device__ __nv_bfloat16 g_Kh[NTOK], g_Kl[NTOK];
__device__ __nv_bfloat16 g_Vh[NTOK], g_Vl[NTOK];
__device__ __nv_bfloat16 g_Wh[DMODEL * DMODEL], g_Wl[DMODEL * DMODEL];
__device__ __nv_bfloat16 g_xh[NTOK], g_xl[NTOK];   // attention output, split

// ---------------------------------------------------------------------------
// PTX helpers
// ---------------------------------------------------------------------------
__device__ __forceinline__ uint32_t cvta_s(const void* p) {
    return (uint32_t)__cvta_generic_to_shared(p);
}
__device__ __forceinline__ void cp16(void* dst, const void* src) {
    asm volatile("cp.async.cg.shared.global [%0], [%1], 16;"
        :: "r"(cvta_s(dst)), "l"(src));
}
__device__ __forceinline__ void cp_commit() {
    asm volatile("cp.async.commit_group;");
}
__device__ __forceinline__ void cp_wait0() {
    asm volatile("cp.async.wait_group 0;");
}
__device__ __forceinline__ void ldsm_x4(uint32_t* r, uint32_t a) {
    asm volatile("ldmatrix.sync.aligned.m8n8.x4.shared.b16 {%0,%1,%2,%3}, [%4];"
        : "=r"(r[0]), "=r"(r[1]), "=r"(r[2]), "=r"(r[3]) : "r"(a));
}
__device__ __forceinline__ void ldsm_x4t(uint32_t* r, uint32_t a) {
    asm volatile("ldmatrix.sync.aligned.m8n8.x4.trans.shared.b16 {%0,%1,%2,%3}, [%4];"
        : "=r"(r[0]), "=r"(r[1]), "=r"(r[2]), "=r"(r[3]) : "r"(a));
}
__device__ __forceinline__ void mma_bf(float* c, const uint32_t* a, const uint32_t* b) {
    asm volatile("mma.sync.aligned.m16n8k16.row.col.f32.bf16.bf16.f32 "
        "{%0,%1,%2,%3}, {%4,%5,%6,%7}, {%8,%9}, {%0,%1,%2,%3};"
        : "+f"(c[0]), "+f"(c[1]), "+f"(c[2]), "+f"(c[3])
        : "r"(a[0]), "r"(a[1]), "r"(a[2]), "r"(a[3]), "r"(b[0]), "r"(b[1]));
}
__device__ __forceinline__ uint32_t packbf(float x, float y) {
    __nv_bfloat162 h = __floats2bfloat162_rn(x, y);
    return *(uint32_t*)&h;
}
__device__ __forceinline__ void split_pack(float x, float y, uint32_t& hi, uint32_t& lo) {
    float hx = __bfloat162float(__float2bfloat16(x));
    float hy = __bfloat162float(__float2bfloat16(y));
    hi = packbf(hx, hy);
    lo = packbf(x - hx, y - hy);
}
__device__ __forceinline__ void split4_store(__nv_bfloat16* hi, __nv_bfloat16* lo, float4 v) {
    float hx = __bfloat162float(__float2bfloat16(v.x));
    float hy = __bfloat162float(__float2bfloat16(v.y));
    float hz = __bfloat162float(__float2bfloat16(v.z));
    float hw = __bfloat162float(__float2bfloat16(v.w));
    uint2 h2; h2.x = packbf(hx, hy);          h2.y = packbf(hz, hw);
    uint2 l2; l2.x = packbf(v.x-hx, v.y-hy);  l2.y = packbf(v.z-hz, v.w-hw);
    *(uint2*)hi = h2;
    *(uint2*)lo = l2;
}

// ---------------------------------------------------------------------------
// Preprocess kernels
// ---------------------------------------------------------------------------
__global__ __launch_bounds__(256)
void prep_qkv(const float* __restrict__ Q, const float* __restrict__ K,
              const float* __restrict__ V)
{
    int i = blockIdx.x * 256 + threadIdx.x;       // float4 index, [0, NTOK/4)
    int e = i * 4;
    float4 q = ((const float4*)Q)[i];
    q.x *= 0.125f; q.y *= 0.125f; q.z *= 0.125f; q.w *= 0.125f;
    split4_store(g_Qh + e, g_Ql + e, q);
    split4_store(g_Kh + e, g_Kl + e, ((const float4*)K)[i]);
    split4_store(g_Vh + e, g_Vl + e, ((const float4*)V)[i]);
}
__global__ __launch_bounds__(256)
void prep_w(const float* __restrict__ W)
{
    int i = blockIdx.x * 256 + threadIdx.x;       // [0, DMODEL*DMODEL/4)
    int e = i * 4;
    split4_store(g_Wh + e, g_Wl + e, ((const float4*)W)[i]);
}

// ---------------------------------------------------------------------------
// Flash attention, mma.sync bf16-split, cp.async 2-stage pipeline.
// grid (16, 32), 256 thr, 2 CTA/SM. Warp w owns rows [16w,16w+16).
// ---------------------------------------------------------------------------
#define KVSZ (BN * PADH)            // elems per K/V sub-array per stage

__global__ __launch_bounds__(256, 2)
void attn_kernel(const float* __restrict__ mask)
{
    extern __shared__ __nv_bfloat16 sb[];
    __nv_bfloat16* sQh = sb;
    __nv_bfloat16* sQl = sQh + BM * PADH;
    __nv_bfloat16* sKV = sQl + BM * PADH;   // [2 stages][Kh,Kl,Vh,Vl][KVSZ]

    const int tid  = threadIdx.x;
    const int warp = tid >> 5;
    const int lane = tid & 31;
    const int g    = lane >> 2;
    const int qd   = lane & 3;
    const int l16  = lane & 15;
    const int mrow = warp * 16;
    const int q0   = blockIdx.x * BM;
    const size_t base = (size_t)blockIdx.y * (S_LEN * DH);

    // ---- prologue: Q tile + KV stage 0 via cp.async ----
    #pragma unroll
    for (int it = 0; it < 4; it++) {
        int i = tid + it * 256;                  // [0,1024) uint4 per array
        int r = i >> 3, c8 = (i & 7) * 8;
        size_t off = base + (size_t)(q0 + r) * DH + c8;
        cp16(sQh + r * PADH + c8, g_Qh + off);
        cp16(sQl + r * PADH + c8, g_Ql + off);
    }
    {
        __nv_bfloat16* st = sKV;                 // stage 0
        #pragma unroll
        for (int it = 0; it < 2; it++) {
            int i = tid + it * 256;              // [0,512) uint4 per array
            int r = i >> 3, c8 = (i & 7) * 8;
            size_t off = base + (size_t)r * DH + c8;
            cp16(st + 0 * KVSZ + r * PADH + c8, g_Kh + off);
            cp16(st + 1 * KVSZ + r * PADH + c8, g_Kl + off);
            cp16(st + 2 * KVSZ + r * PADH + c8, g_Vh + off);
            cp16(st + 3 * KVSZ + r * PADH + c8, g_Vl + off);
        }
    }
    cp_commit();

    float o[8][4];
    #pragma unroll
    for (int n = 0; n < 8; n++)
        #pragma unroll
        for (int c = 0; c < 4; c++) o[n][c] = 0.0f;
    float m0r = -1e30f, m1r = -1e30f, l0r = 0.0f, l1r = 0.0f;

    const float* mk0 = mask + (size_t)(q0 + mrow + g) * S_LEN;
    const float* mk1 = mk0 + 8 * S_LEN;
    const int t8 = lane >> 3;

    const uint32_t qh32 = cvta_s(sQh), ql32 = cvta_s(sQl);

    for (int kt = 0; kt < S_LEN; kt += BN) {
        cp_wait0();
        __syncthreads();     // data visible to all warps; compute(prev) done

        // ---- issue loads for next tile into alternate stage ----
        if (kt + BN < S_LEN) {
            __nv_bfloat16* st = sKV + (((kt / BN) + 1) & 1) * 4 * KVSZ;
            #pragma unroll
            for (int it = 0; it < 2; it++) {
                int i = tid + it * 256;
                int r = i >> 3, c8 = (i & 7) * 8;
                size_t off = base + (size_t)(kt + BN + r) * DH + c8;
                cp16(st + 0 * KVSZ + r * PADH + c8, g_Kh + off);
                cp16(st + 1 * KVSZ + r * PADH + c8, g_Kl + off);
                cp16(st + 2 * KVSZ + r * PADH + c8, g_Vh + off);
                cp16(st + 3 * KVSZ + r * PADH + c8, g_Vl + off);
            }
        }
        cp_commit();

        __nv_bfloat16* st = sKV + ((kt / BN) & 1) * 4 * KVSZ;
        const uint32_t kh32 = cvta_s(st);
        const uint32_t kl32 = cvta_s(st + 1 * KVSZ);
        const uint32_t vh32 = cvta_s(st + 2 * KVSZ);
        const uint32_t vl32 = cvta_s(st + 3 * KVSZ);

        // ---- S = Q @ K^T (3-product split, paired-B x4 loads) ----
        float s[8][4];
        #pragma unroll
        for (int n = 0; n < 8; n++)
            #pragma unroll
            for (int c = 0; c < 4; c++) s[n][c] = 0.0f;

        #pragma unroll
        for (int k = 0; k < 4; k++) {
            uint32_t ah[4], al[4];
            uint32_t ao = (uint32_t)(((mrow + l16) * PADH + k * 16 + (lane >> 4) * 8) * 2);
            ldsm_x4(ah, qh32 + ao);
            ldsm_x4(al, ql32 + ao);
            #pragma unroll
            for (int np = 0; np < 4; np++) {
                uint32_t bh[4], bl[4];
                uint32_t bo = (uint32_t)((((2 * np + (t8 >> 1)) * 8 + (lane & 7)) * PADH
                                          + k * 16 + (t8 & 1) * 8) * 2);
                ldsm_x4(bh, kh32 + bo);
                ldsm_x4(bl, kl32 + bo);
                mma_bf(s[2*np  ], ah, bh);     mma_bf(s[2*np  ], ah, bl);     mma_bf(s[2*np  ], al, bh);
                mma_bf(s[2*np+1], ah, bh + 2); mma_bf(s[2*np+1], ah, bl + 2); mma_bf(s[2*np+1], al, bh + 2);
            }
        }

        // ---- add mask ----
        #pragma unroll
        for (int n = 0; n < 8; n++) {
            float2 a = *(const float2*)(mk0 + kt + n * 8 + qd * 2);
            float2 b = *(const float2*)(mk1 + kt + n * 8 + qd * 2);
            s[n][0] += a.x; s[n][1] += a.y; s[n][2] += b.x; s[n][3] += b.y;
        }

        // ---- online softmax ----
        float mx0 = -1e30f, mx1 = -1e30f;
        #pragma unroll
        for (int n = 0; n < 8; n++) {
            mx0 = fmaxf(mx0, fmaxf(s[n][0], s[n][1]));
            mx1 = fmaxf(mx1, fmaxf(s[n][2], s[n][3]));
        }
        mx0 = fmaxf(mx0, __shfl_xor_sync(0xffffffffu, mx0, 1));
        mx0 = fmaxf(mx0, __shfl_xor_sync(0xffffffffu, mx0, 2));
        mx1 = fmaxf(mx1, __shfl_xor_sync(0xffffffffu, mx1, 1));
        mx1 = fmaxf(mx1, __shfl_xor_sync(0xffffffffu, mx1, 2));
        float mn0 = fmaxf(m0r, mx0), mn1 = fmaxf(m1r, mx1);
        float c0 = __expf(m0r - mn0), c1 = __expf(m1r - mn1);
        m0r = mn0; m1r = mn1;

        float s0 = 0.0f, s1 = 0.0f;
        #pragma unroll
        for (int n = 0; n < 8; n++) {
            s[n][0] = __expf(s[n][0] - mn0); s[n][1] = __expf(s[n][1] - mn0);
            s[n][2] = __expf(s[n][2] - mn1); s[n][3] = __expf(s[n][3] - mn1);
            s0 += s[n][0] + s[n][1];
            s1 += s[n][2] + s[n][3];
        }
        s0 += __shfl_xor_sync(0xffffffffu, s0, 1);
        s0 += __shfl_xor_sync(0xffffffffu, s0, 2);
        s1 += __shfl_xor_sync(0xffffffffu, s1, 1);
        s1 += __shfl_xor_sync(0xffffffffu, s1, 2);
        l0r = l0r * c0 + s0;
        l1r = l1r * c1 + s1;

        #pragma unroll
        for (int n = 0; n < 8; n++) {
            o[n][0] *= c0; o[n][1] *= c0; o[n][2] *= c1; o[n][3] *= c1;
        }

        // ---- O += P @ V (P split in regs, paired-B x4 trans loads) ----
        #pragma unroll
        for (int k = 0; k < 4; k++) {
            uint32_t ph[4], pl[4];
            split_pack(s[2*k  ][0], s[2*k  ][1], ph[0], pl[0]);
            split_pack(s[2*k  ][2], s[2*k  ][3], ph[1], pl[1]);
            split_pack(s[2*k+1][0], s[2*k+1][1], ph[2], pl[2]);
            split_pack(s[2*k+1][2], s[2*k+1][3], ph[3], pl[3]);
            #pragma unroll
            for (int np = 0; np < 4; np++) {
                uint32_t bh[4], bl[4];
                uint32_t bo = (uint32_t)(((k * 16 + (t8 & 1) * 8 + (lane & 7)) * PADH
                                          + (2 * np + (t8 >> 1)) * 8) * 2);
                ldsm_x4t(bh, vh32 + bo);
                ldsm_x4t(bl, vl32 + bo);
                mma_bf(o[2*np  ], ph, bh);     mma_bf(o[2*np  ], ph, bl);     mma_bf(o[2*np  ], pl, bh);
                mma_bf(o[2*np+1], ph, bh + 2); mma_bf(o[2*np+1], ph, bl + 2); mma_bf(o[2*np+1], pl, bh + 2);
            }
        }
    }

    // ---- epilogue: O /= l, split-store to g_xh/g_xl ----
    float i0 = 1.0f / l0r, i1 = 1.0f / l1r;
    size_t r0off = base + (size_t)(q0 + mrow + g) * DH;
    size_t r1off = r0off + 8 * DH;
    #pragma unroll
    for (int n = 0; n < 8; n++) {
        uint32_t h, l;
        split_pack(o[n][0] * i0, o[n][1] * i0, h, l);
        *(uint32_t*)(g_xh + r0off + n * 8 + qd * 2) = h;
        *(uint32_t*)(g_xl + r0off + n * 8 + qd * 2) = l;
        split_pack(o[n][2] * i1, o[n][3] * i1, h, l);
        *(uint32_t*)(g_xh + r1off + n * 8 + qd * 2) = h;
        *(uint32_t*)(g_xl + r1off + n * 8 + qd * 2) = l;
    }
}

// ---------------------------------------------------------------------------
// Projection: out[4096,1024] = x @ W^T + b, cp.async 2-stage pipeline.
// grid (16, 32), 256 threads, 2 CTA/SM.
// ---------------------------------------------------------------------------
#define XSZ (BM * PADH)
#define WSZ (BN * PADH)
#define PSTG (2 * XSZ + 2 * WSZ)    // elems per proj stage

__global__ __launch_bounds__(256, 2)
void proj_kernel(const float* __restrict__ bias, float* __restrict__ out)
{
    extern __shared__ __nv_bfloat16 sb[];  // [2 stages][Xh,Xl,Wh,Wl]

    const int tid  = threadIdx.x;
    const int warp = tid >> 5;
    const int lane = tid & 31;
    const int g    = lane >> 2;
    const int qd   = lane & 3;
    const int l16  = lane & 15;
    const int mrow = warp * 16;
    const int n0   = blockIdx.x * BN;
    const int m0   = blockIdx.y * BM;
    const int t8   = lane >> 3;

    float o[8][4];
    #pragma unroll
    for (int n = 0; n < 8; n++)
        #pragma unroll
        for (int c = 0; c < 4; c++) o[n][c] = 0.0f;

    // ---- prologue: stage 0 ----
    {
        __nv_bfloat16* st = sb;
        #pragma unroll
        for (int it = 0; it < 4; it++) {
            int i = tid + it * 256;
            int r = i >> 3, c8 = (i & 7) * 8;
            size_t off = (size_t)(m0 + r) * DMODEL + c8;
            cp16(st + r * PADH + c8,       g_xh + off);
            cp16(st + XSZ + r * PADH + c8, g_xl + off);
        }
        #pragma unroll
        for (int it = 0; it < 2; it++) {
            int i = tid + it * 256;
            int r = i >> 3, c8 = (i & 7) * 8;
            size_t off = (size_t)(n0 + r) * DMODEL + c8;
            cp16(st + 2 * XSZ + r * PADH + c8,       g_Wh + off);
            cp16(st + 2 * XSZ + WSZ + r * PADH + c8, g_Wl + off);
        }
    }
    cp_commit();

    for (int kt = 0; kt < DMODEL; kt += 64) {
        cp_wait0();
        __syncthreads();

        if (kt + 64 < DMODEL) {
            __nv_bfloat16* st = sb + (((kt / 64) + 1) & 1) * PSTG;
            #pragma unroll
            for (int it = 0; it < 4; it++) {
                int i = tid + it * 256;
                int r = i >> 3, c8 = (i & 7) * 8;
                size_t off = (size_t)(m0 + r) * DMODEL + kt + 64 + c8;
                cp16(st + r * PADH + c8,       g_xh + off);
                cp16(st + XSZ + r * PADH + c8, g_xl + off);
            }
            #pragma unroll
            for (int it = 0; it < 2; it++) {
                int i = tid + it * 256;
                int r = i >> 3, c8 = (i & 7) * 8;
                size_t off = (size_t)(n0 + r) * DMODEL + kt + 64 + c8;
                cp16(st + 2 * XSZ + r * PADH + c8,       g_Wh + off);
                cp16(st + 2 * XSZ + WSZ + r * PADH + c8, g_Wl + off);
            }
        }
        cp_commit();

        __nv_bfloat16* st = sb + ((kt / 64) & 1) * PSTG;
        const uint32_t xh32 = cvta_s(st);
        const uint32_t xl32 = cvta_s(st + XSZ);
        const uint32_t wh32 = cvta_s(st + 2 * XSZ);
        const uint32_t wl32 = cvta_s(st + 2 * XSZ + WSZ);

        #pragma unroll
        for (int k = 0; k < 4; k++) {
            uint32_t ah[4], al[4];
            uint32_t ao = (uint32_t)(((mrow + l16) * PADH + k * 16 + (lane >> 4) * 8) * 2);
            ldsm_x4(ah, xh32 + ao);
            ldsm_x4(al, xl32 + ao);
            #pragma unroll
            for (int np = 0; np < 4; np++) {
                uint32_t bh[4], bl[4];
                uint32_t bo = (uint32_t)((((2 * np + (t8 >> 1)) * 8 + (lane & 7)) * PADH
                                          + k * 16 + (t8 & 1) * 8) * 2);
                ldsm_x4(bh, wh32 + bo);
                ldsm_x4(bl, wl32 + bo);
                mma_bf(o[2*np  ], ah, bh);     mma_bf(o[2*np  ], ah, bl);     mma_bf(o[2*np  ], al, bh);
                mma_bf(o[2*np+1], ah, bh + 2); mma_bf(o[2*np+1], ah, bl + 2); mma_bf(o[2*np+1], al, bh + 2);
            }
        }
    }

    float* od0 = out + (size_t)(m0 + mrow + g) * DMODEL + n0;
    float* od1 = od0 + 8 * DMODEL;
    #pragma unroll
    for (int n = 0; n < 8; n++) {
        float2 bv = *(const float2*)(bias + n0 + n * 8 + qd * 2);
        float2 a; a.x = o[n][0] + bv.x; a.y = o[n][1] + bv.y;
        float2 b; b.x = o[n][2] + bv.x; b.y = o[n][3] + bv.y;
        *(float2*)(od0 + n * 8 + qd * 2) = a;
        *(float2*)(od1 + n * 8 + qd * 2) = b;
    }
}

// ---------------------------------------------------------------------------
extern "C" void kernel_launch(void* const* d_in, const int* in_sizes, int n_in,
                              void* d_out, int out_size)
{
    const float* Q    = (const float*)d_in[0];
    const float* K    = (const float*)d_in[1];
    const float* V    = (const float*)d_in[2];
    const float* mask = (const float*)d_in[3];
    const float* W    = (const float*)d_in[4];
    const float* bias = (const float*)d_in[5];
    float* out        = (float*)d_out;

    prep_qkv<<<NTOK / 4 / 256, 256>>>(Q, K, V);
    prep_w<<<DMODEL * DMODEL / 4 / 256, 256>>>(W);

    // attn smem: (2*128 + 2*4*64) * 72 * 2B = 110592 B
    const int attn_smem = (2 * BM + 8 * BN) * PADH * (int)sizeof(__nv_bfloat16);
    cudaFuncSetAttribute(attn_kernel, cudaFuncAttributeMaxDynamicSharedMemorySize,
                         attn_smem);
    // proj smem: 2 stages * (2*128 + 2*64) * 72 * 2B = 110592 B
    const int proj_smem = 2 * PSTG * (int)sizeof(__nv_bfloat16);
    cudaFuncSetAttribute(proj_kernel, cudaFuncAttributeMaxDynamicSharedMemorySize,
                         proj_smem);

    dim3 agrid(S_LEN / BM, BATCH * HEADS);        // (16, 32)
    attn_kernel<<<agrid, 256, attn_smem>>>(mask);

    dim3 pgrid(DMODEL / BN, BATCH * S_LEN / BM);  // (16, 32)
    proj_kernel<<<pgrid, 256, proj_smem>>>(bias, out);
}